// round 16
// baseline (speedup 1.0000x reference)
#include <cuda_runtime.h>
#include <cuda_bf16.h>

// Problem constants
#define N 4096
#define D 512
#define NC 100          // real classes
#define NCP 128         // padded classes
#define ROWS_B 32       // rows per GEMM block
#define KT 32           // k-tile
#define NBLK (N / ROWS_B)   // 128 gemm blocks
#define TPB 512             // 16 warps: (m, nq, kh)

// Double-buffered scratch (parity protocol proven in R14).
__device__ float g_rscale[N];                        // per-row 1/||txt_i||
__device__ float g_d[N];                             // per-row <img_n, txt_n>
__device__ __align__(16) float g_G[2][NC * D];       // class sums of img_n
__device__ int    g_cnt[2][NCP];                     // class counts
__device__ double g_neg[2];                          // neg accumulator
__device__ double g_sumd[2];                         // sum_i d_i
__device__ double g_sumexpd[2];                      // sum_i exp(d_i)
__device__ unsigned int g_fin[2];                    // epilogue ticket
__device__ unsigned int g_parity;                    // current buffer index

__device__ __forceinline__ unsigned tf32(float x) {
    unsigned r;
    asm("cvt.rna.tf32.f32 %0, %1;" : "=r"(r) : "f"(x));
    return r;
}

// ---------------------------------------------------------------------------
// Kernel 1 (R14-proven, unchanged): normalize, rscale + d_i, v4-REDG -> G[p].
// ---------------------------------------------------------------------------
__global__ void __launch_bounds__(128) rownorm_kernel(
    const float* __restrict__ img,
    const float* __restrict__ txt,
    const int* __restrict__ labels)
{
    const int i    = blockIdx.x;
    const int tid  = threadIdx.x;
    const int lane = tid & 31;
    const int warp = tid >> 5;
    const unsigned p = g_parity;

    const float4 a = reinterpret_cast<const float4*>(img + (size_t)i * D)[tid];
    const float4 b = reinterpret_cast<const float4*>(txt + (size_t)i * D)[tid];

    float sii = a.x*a.x + a.y*a.y + a.z*a.z + a.w*a.w;
    float stt = b.x*b.x + b.y*b.y + b.z*b.z + b.w*b.w;
    float sit = a.x*b.x + a.y*b.y + a.z*b.z + a.w*b.w;

    #pragma unroll
    for (int off = 16; off > 0; off >>= 1) {
        sii += __shfl_xor_sync(0xffffffffu, sii, off);
        stt += __shfl_xor_sync(0xffffffffu, stt, off);
        sit += __shfl_xor_sync(0xffffffffu, sit, off);
    }
    __shared__ float red[3][4];
    if (lane == 0) { red[0][warp] = sii; red[1][warp] = stt; red[2][warp] = sit; }
    __syncthreads();
    sii = red[0][0] + red[0][1] + red[0][2] + red[0][3];
    stt = red[1][0] + red[1][1] + red[1][2] + red[1][3];
    sit = red[2][0] + red[2][1] + red[2][2] + red[2][3];

    const float rimg = rsqrtf(sii);
    const float rtxt = rsqrtf(stt);
    int c = labels[i];
    c = min(max(c, 0), NC - 1);

    float* gc = g_G[p] + (size_t)c * D + tid * 4;
    asm volatile("red.global.add.v4.f32 [%0], {%1, %2, %3, %4};"
                 :: "l"(gc), "f"(a.x * rimg), "f"(a.y * rimg),
                    "f"(a.z * rimg), "f"(a.w * rimg)
                 : "memory");

    if (tid == 0) {
        g_rscale[i] = rtxt;
        g_d[i] = sit * rimg * rtxt;
        atomicAdd(&g_cnt[p][c], 1);
    }
}

// ---------------------------------------------------------------------------
// Kernel 2: tf32 mma GEMM, 16 warps via k-split + neg + loss + parity clean.
// grid = 128 blocks, 512 threads.
// Warp (kh = w>>3, m = w&1, nq = (w>>1)&3): rows 16m..+15, classes 32nq..+31,
// k-subtiles {2kh, 2kh+1} of each 32-k tile. kh accumulators merged via smem.
// Delta vs R15: __expf (MUFU.EX2 fast path) in the 16-term epilogue instead
// of libm expf (~10-15 instr each) — the diagnosed fixed serial cost.
// ---------------------------------------------------------------------------
__global__ void __launch_bounds__(TPB) gemm_neg_kernel(
    const float* __restrict__ txt,
    float* __restrict__ out)
{
    __shared__ float As[ROWS_B][36];     // [row][k], tf32 bits
    __shared__ float Bs[NCP][36];        // [class][k], tf32 bits
    __shared__ float nsm[NCP];
    __shared__ float rs[ROWS_B];
    __shared__ float Ssm[ROWS_B][4];
    __shared__ float sacc[8][32][16];    // kh=1 accumulator spill (16KB)
    __shared__ double bred[8][3];

    const int tid  = threadIdx.x;
    const int lane = tid & 31;
    const int warp = tid >> 5;
    const int w8   = warp & 7;           // (m, nq) id
    const int kh   = warp >> 3;          // k-half 0/1
    const int g    = lane >> 2;
    const int tig  = lane & 3;
    const int m    = w8 & 1;
    const int nq   = w8 >> 1;
    const int row0 = blockIdx.x * ROWS_B;
    const unsigned p = g_parity;
    const unsigned q = 1u - p;

    // ---- zero-wait cleaning of the IDLE buffer q (R14-proven) ----
    if (tid < 100) {
        const float4 z4 = make_float4(0.f, 0.f, 0.f, 0.f);
        reinterpret_cast<float4*>(g_G[q])[blockIdx.x * 100 + tid] = z4;
    }
    if (blockIdx.x == 0) {
        if (tid < NCP) g_cnt[q][tid] = 0;
        if (tid == 0) { g_neg[q] = 0.0; g_sumd[q] = 0.0; g_sumexpd[q] = 0.0; g_fin[q] = 0u; }
    }

    if (tid < NCP) nsm[tid] = (float)g_cnt[p][tid];
    if (tid < ROWS_B) rs[tid] = g_rscale[row0 + tid];

    float acc[4][4] = {};                // [n-tile][c0..c3], this warp's k-half

    // staging addressing: A by tid<256 (256 float4), B by all (2 float4 each)
    const int ar  = tid >> 3;            // valid when tid<256: row 0..31
    const int ak4 = (tid & 7) * 4;
    const float4 zero4 = make_float4(0.f, 0.f, 0.f, 0.f);

    float4 aReg;
    float4 bReg[2];

    // prefetch tile 0
    if (tid < 256)
        aReg = *reinterpret_cast<const float4*>(&txt[(size_t)(row0 + ar) * D + ak4]);
    #pragma unroll
    for (int e = 0; e < 2; e++) {
        int idx = tid + e * TPB;
        int c = idx >> 3, k4 = (idx & 7) * 4;
        bReg[e] = (c < NC)
            ? *reinterpret_cast<const float4*>(&g_G[p][(size_t)c * D + k4])
            : zero4;
    }
    __syncthreads();   // rs / nsm visible
    const float ascale = (tid < 256) ? rs[ar] : 0.f;

    for (int t = 0; t < D / KT; t++) {
        if (tid < 256) {
            float4 av;
            av.x = __uint_as_float(tf32(aReg.x * ascale));
            av.y = __uint_as_float(tf32(aReg.y * ascale));
            av.z = __uint_as_float(tf32(aReg.z * ascale));
            av.w = __uint_as_float(tf32(aReg.w * ascale));
            *reinterpret_cast<float4*>(&As[ar][ak4]) = av;
        }
        #pragma unroll
        for (int e = 0; e < 2; e++) {
            int idx = tid + e * TPB;
            int c = idx >> 3, k4 = (idx & 7) * 4;
            float4 bv;
            bv.x = __uint_as_float(tf32(bReg[e].x));
            bv.y = __uint_as_float(tf32(bReg[e].y));
            bv.z = __uint_as_float(tf32(bReg[e].z));
            bv.w = __uint_as_float(tf32(bReg[e].w));
            *reinterpret_cast<float4*>(&Bs[c][k4]) = bv;
        }
        __syncthreads();

        // prefetch next tile
        if (t < D / KT - 1) {
            int k0 = (t + 1) * KT;
            if (tid < 256)
                aReg = *reinterpret_cast<const float4*>(&txt[(size_t)(row0 + ar) * D + k0 + ak4]);
            #pragma unroll
            for (int e = 0; e < 2; e++) {
                int idx = tid + e * TPB;
                int c = idx >> 3, k4 = (idx & 7) * 4;
                bReg[e] = (c < NC)
                    ? *reinterpret_cast<const float4*>(&g_G[p][(size_t)c * D + k0 + k4])
                    : zero4;
            }
        }

        // compute: this warp's 2 k-subtiles (of the tile's 4)
        #pragma unroll
        for (int j = 0; j < 2; j++) {
            const int kk0 = (2 * kh + j) * 8;
            const unsigned a0 = __float_as_uint(As[16*m + g    ][kk0 + tig]);
            const unsigned a1 = __float_as_uint(As[16*m + g + 8][kk0 + tig]);
            const unsigned a2 = __float_as_uint(As[16*m + g    ][kk0 + tig + 4]);
            const unsigned a3 = __float_as_uint(As[16*m + g + 8][kk0 + tig + 4]);
            #pragma unroll
            for (int nt = 0; nt < 4; nt++) {
                const int cb = 32*nq + 8*nt + g;
                const unsigned b0 = __float_as_uint(Bs[cb][kk0 + tig]);
                const unsigned b1 = __float_as_uint(Bs[cb][kk0 + tig + 4]);
                asm volatile(
                    "mma.sync.aligned.m16n8k8.row.col.f32.tf32.tf32.f32 "
                    "{%0,%1,%2,%3}, {%4,%5,%6,%7}, {%8,%9}, {%0,%1,%2,%3};"
                    : "+f"(acc[nt][0]), "+f"(acc[nt][1]),
                      "+f"(acc[nt][2]), "+f"(acc[nt][3])
                    : "r"(a0), "r"(a1), "r"(a2), "r"(a3), "r"(b0), "r"(b1));
            }
        }
        __syncthreads();
    }

    // ---- merge kh=1 accumulators into kh=0 warps ----
    if (kh == 1) {
        #pragma unroll
        for (int nt = 0; nt < 4; nt++)
            #pragma unroll
            for (int e = 0; e < 4; e++)
                sacc[w8][lane][nt * 4 + e] = acc[nt][e];
    }
    __syncthreads();
    if (kh == 0) {
        #pragma unroll
        for (int nt = 0; nt < 4; nt++)
            #pragma unroll
            for (int e = 0; e < 4; e++)
                acc[nt][e] += sacc[w8][lane][nt * 4 + e];
    }

    // ---- Epilogue (R10-validated layout), kh=0 warps only ----
    const int r0 = 16*m + g, r1 = r0 + 8;
    if (kh == 0) {
        float s0 = 0.f, s1 = 0.f;
        #pragma unroll
        for (int nt = 0; nt < 4; nt++) {
            s0 += acc[nt][0] + acc[nt][1];
            s1 += acc[nt][2] + acc[nt][3];
        }
        s0 += __shfl_xor_sync(0xffffffffu, s0, 1);
        s0 += __shfl_xor_sync(0xffffffffu, s0, 2);
        s1 += __shfl_xor_sync(0xffffffffu, s1, 1);
        s1 += __shfl_xor_sync(0xffffffffu, s1, 2);
        if (tig == 0) { Ssm[r0][nq] = s0; Ssm[r1][nq] = s1; }
    }
    __syncthreads();

    if (kh == 0) {
        const float S0 = Ssm[r0][0] + Ssm[r0][1] + Ssm[r0][2] + Ssm[r0][3];
        const float S1 = Ssm[r1][0] + Ssm[r1][1] + Ssm[r1][2] + Ssm[r1][3];
        float pn = 0.f;
        #pragma unroll
        for (int nt = 0; nt < 4; nt++) {
            const int cA = 32*nq + 8*nt + 2*tig;
            const float nA = nsm[cA], nB = nsm[cA + 1];
            // __expf: FMUL + MUFU.EX2 (vs ~10-15 instr libm expf).
            // |S-C| <= ~40 -> rel err ~2e-6, negligible vs 1e-3 tolerance.
            pn += nA * __expf(S0 - acc[nt][0]) + nB * __expf(S0 - acc[nt][1]);
            pn += nA * __expf(S1 - acc[nt][2]) + nB * __expf(S1 - acc[nt][3]);
        }
        #pragma unroll
        for (int off = 16; off > 0; off >>= 1)
            pn += __shfl_xor_sync(0xffffffffu, pn, off);

        double warp_sd = 0.0, warp_se = 0.0;
        if (warp == 0) {
            const float dv = g_d[row0 + lane];
            double sd = (double)dv;
            double se = (double)__expf(dv);
            #pragma unroll
            for (int off = 16; off > 0; off >>= 1) {
                sd += __shfl_xor_sync(0xffffffffu, sd, off);
                se += __shfl_xor_sync(0xffffffffu, se, off);
            }
            warp_sd = sd; warp_se = se;
        }
        if (lane == 0) { bred[w8][0] = (double)pn; bred[w8][1] = warp_sd; bred[w8][2] = warp_se; }
    }
    __syncthreads();

    if (tid == 0) {
        double bneg = 0.0;
        #pragma unroll
        for (int w = 0; w < 8; w++) bneg += bred[w][0];
        atomicAdd(&g_neg[p], bneg);
        atomicAdd(&g_sumd[p], bred[0][1]);
        atomicAdd(&g_sumexpd[p], bred[0][2]);
        __threadfence();   // orders scalar adds + buffer-q cleaning stores
        unsigned t = atomicAdd(&g_fin[p], 1u);
        if (t == NBLK - 1) {
            // loss = N*log(neg) + sumexp/neg - sumd (validated across rounds)
            const double neg  = atomicAdd(&g_neg[p], 0.0);
            const double sd   = atomicAdd(&g_sumd[p], 0.0);
            const double sexp = atomicAdd(&g_sumexpd[p], 0.0);
            out[0] = (float)((double)N * log(neg) + sexp / neg - sd);
            __threadfence();
            g_parity = q;
        }
    }
}

// ---------------------------------------------------------------------------
extern "C" void kernel_launch(void* const* d_in, const int* in_sizes, int n_in,
                              void* d_out, int out_size) {
    const float* img    = (const float*)d_in[0];
    const float* txt    = (const float*)d_in[1];
    const int*   labels = (const int*)d_in[2];
    float* out = (float*)d_out;

    rownorm_kernel<<<N, 128>>>(img, txt, labels);
    gemm_neg_kernel<<<NBLK, TPB>>>(txt, out);
}

// round 17
// speedup vs baseline: 1.0769x; 1.0769x over previous
#include <cuda_runtime.h>
#include <cuda_bf16.h>

// Problem constants
#define N 4096
#define D 512
#define NC 100          // real classes
#define NCP 128         // padded classes
#define ROWS_B 32       // rows per GEMM block
#define KT 64           // k-tile (R17: doubled, halves barrier rounds)
#define NT (D / KT)     // 8 tiles
#define NBLK (N / ROWS_B)   // 128 gemm blocks
#define TPB 512             // 16 warps: (m, nq, kh)

// Double-buffered scratch (parity protocol proven in R14).
__device__ float g_rscale[N];                        // per-row 1/||txt_i||
__device__ float g_d[N];                             // per-row <img_n, txt_n>
__device__ __align__(16) float g_G[2][NC * D];       // class sums of img_n
__device__ int    g_cnt[2][NCP];                     // class counts
__device__ double g_neg[2];                          // neg accumulator
__device__ double g_sumd[2];                         // sum_i d_i
__device__ double g_sumexpd[2];                      // sum_i exp(d_i)
__device__ unsigned int g_fin[2];                    // epilogue ticket
__device__ unsigned int g_parity;                    // current buffer index

__device__ __forceinline__ unsigned tf32(float x) {
    unsigned r;
    asm("cvt.rna.tf32.f32 %0, %1;" : "=r"(r) : "f"(x));
    return r;
}

// ---------------------------------------------------------------------------
// Kernel 1 (R14-proven, unchanged): normalize, rscale + d_i, v4-REDG -> G[p].
// ---------------------------------------------------------------------------
__global__ void __launch_bounds__(128) rownorm_kernel(
    const float* __restrict__ img,
    const float* __restrict__ txt,
    const int* __restrict__ labels)
{
    const int i    = blockIdx.x;
    const int tid  = threadIdx.x;
    const int lane = tid & 31;
    const int warp = tid >> 5;
    const unsigned p = g_parity;

    const float4 a = reinterpret_cast<const float4*>(img + (size_t)i * D)[tid];
    const float4 b = reinterpret_cast<const float4*>(txt + (size_t)i * D)[tid];

    float sii = a.x*a.x + a.y*a.y + a.z*a.z + a.w*a.w;
    float stt = b.x*b.x + b.y*b.y + b.z*b.z + b.w*b.w;
    float sit = a.x*b.x + a.y*b.y + a.z*b.z + a.w*b.w;

    #pragma unroll
    for (int off = 16; off > 0; off >>= 1) {
        sii += __shfl_xor_sync(0xffffffffu, sii, off);
        stt += __shfl_xor_sync(0xffffffffu, stt, off);
        sit += __shfl_xor_sync(0xffffffffu, sit, off);
    }
    __shared__ float red[3][4];
    if (lane == 0) { red[0][warp] = sii; red[1][warp] = stt; red[2][warp] = sit; }
    __syncthreads();
    sii = red[0][0] + red[0][1] + red[0][2] + red[0][3];
    stt = red[1][0] + red[1][1] + red[1][2] + red[1][3];
    sit = red[2][0] + red[2][1] + red[2][2] + red[2][3];

    const float rimg = rsqrtf(sii);
    const float rtxt = rsqrtf(stt);
    int c = labels[i];
    c = min(max(c, 0), NC - 1);

    float* gc = g_G[p] + (size_t)c * D + tid * 4;
    asm volatile("red.global.add.v4.f32 [%0], {%1, %2, %3, %4};"
                 :: "l"(gc), "f"(a.x * rimg), "f"(a.y * rimg),
                    "f"(a.z * rimg), "f"(a.w * rimg)
                 : "memory");

    if (tid == 0) {
        g_rscale[i] = rtxt;
        g_d[i] = sit * rimg * rtxt;
        atomicAdd(&g_cnt[p][c], 1);
    }
}

// ---------------------------------------------------------------------------
// Kernel 2: tf32 mma GEMM, KT=64 (8 serial tile rounds instead of 16),
// 16 warps via k-split + neg + loss + parity clean.
// Warp (kh = w>>3, m = w&1, nq = (w>>1)&3): rows 16m..+15, classes 32nq..+31,
// k-subtiles {4kh .. 4kh+3} of each 64-k tile.
// ---------------------------------------------------------------------------
__global__ void __launch_bounds__(TPB) gemm_neg_kernel(
    const float* __restrict__ txt,
    float* __restrict__ out)
{
    __shared__ float As[ROWS_B][KT + 4];   // [row][k], tf32 bits, stride 68
    __shared__ float Bs[NCP][KT + 4];      // [class][k], tf32 bits, stride 68
    __shared__ float nsm[NCP];
    __shared__ float rs[ROWS_B];
    __shared__ float Ssm[ROWS_B][4];
    __shared__ double bred[8][3];
    // kh=1 accumulator spill aliased onto Bs (dead after mainloop; barrier-
    // separated). Needs 8*32*16*4 = 16KB <= sizeof(Bs) = 34.8KB.
    float* saccf = &Bs[0][0];

    const int tid  = threadIdx.x;
    const int lane = tid & 31;
    const int warp = tid >> 5;
    const int w8   = warp & 7;           // (m, nq) id
    const int kh   = warp >> 3;          // k-half 0/1
    const int g    = lane >> 2;
    const int tig  = lane & 3;
    const int m    = w8 & 1;
    const int nq   = w8 >> 1;
    const int row0 = blockIdx.x * ROWS_B;
    const unsigned p = g_parity;
    const unsigned q = 1u - p;

    // ---- zero-wait cleaning of the IDLE buffer q (R14-proven) ----
    if (tid < 100) {
        const float4 z4 = make_float4(0.f, 0.f, 0.f, 0.f);
        reinterpret_cast<float4*>(g_G[q])[blockIdx.x * 100 + tid] = z4;
    }
    if (blockIdx.x == 0) {
        if (tid < NCP) g_cnt[q][tid] = 0;
        if (tid == 0) { g_neg[q] = 0.0; g_sumd[q] = 0.0; g_sumexpd[q] = 0.0; g_fin[q] = 0u; }
    }

    if (tid < NCP) nsm[tid] = (float)g_cnt[p][tid];
    if (tid < ROWS_B) rs[tid] = g_rscale[row0 + tid];

    float acc[4][4] = {};                // [n-tile][c0..c3], this warp's k-half

    // staging addressing:
    // A tile = 32 rows x 64 k = 512 float4 -> 1 per thread
    // B tile = 128 classes x 64 k = 2048 float4 -> 4 per thread
    const int s_ar = tid >> 4;           // A row 0..31
    const int s_ak = (tid & 15) * 4;     // A k offset 0..60
    const float4 zero4 = make_float4(0.f, 0.f, 0.f, 0.f);

    float4 aReg;
    float4 bReg[4];

    // prefetch tile 0
    aReg = *reinterpret_cast<const float4*>(&txt[(size_t)(row0 + s_ar) * D + s_ak]);
    #pragma unroll
    for (int e = 0; e < 4; e++) {
        int idx = tid + e * TPB;
        int c = idx >> 4, k4 = (idx & 15) * 4;
        bReg[e] = (c < NC)
            ? *reinterpret_cast<const float4*>(&g_G[p][(size_t)c * D + k4])
            : zero4;
    }
    __syncthreads();   // rs / nsm visible
    const float ascale = rs[s_ar];

    for (int t = 0; t < NT; t++) {
        // commit prefetched tile to smem as tf32 bits
        {
            float4 av;
            av.x = __uint_as_float(tf32(aReg.x * ascale));
            av.y = __uint_as_float(tf32(aReg.y * ascale));
            av.z = __uint_as_float(tf32(aReg.z * ascale));
            av.w = __uint_as_float(tf32(aReg.w * ascale));
            *reinterpret_cast<float4*>(&As[s_ar][s_ak]) = av;
        }
        #pragma unroll
        for (int e = 0; e < 4; e++) {
            int idx = tid + e * TPB;
            int c = idx >> 4, k4 = (idx & 15) * 4;
            float4 bv;
            bv.x = __uint_as_float(tf32(bReg[e].x));
            bv.y = __uint_as_float(tf32(bReg[e].y));
            bv.z = __uint_as_float(tf32(bReg[e].z));
            bv.w = __uint_as_float(tf32(bReg[e].w));
            *reinterpret_cast<float4*>(&Bs[c][k4]) = bv;
        }

        // issue next tile's LDGs BEFORE the barrier: latency window now spans
        // sync + compute + sync instead of compute only.
        if (t < NT - 1) {
            const int k0 = (t + 1) * KT;
            aReg = *reinterpret_cast<const float4*>(&txt[(size_t)(row0 + s_ar) * D + k0 + s_ak]);
            #pragma unroll
            for (int e = 0; e < 4; e++) {
                int idx = tid + e * TPB;
                int c = idx >> 4, k4 = (idx & 15) * 4;
                bReg[e] = (c < NC)
                    ? *reinterpret_cast<const float4*>(&g_G[p][(size_t)c * D + k0 + k4])
                    : zero4;
            }
        }

        __syncthreads();   // tile t staged

        // compute: this warp's 4 k-subtiles (of the tile's 8)
        #pragma unroll
        for (int j = 0; j < 4; j++) {
            const int kk0 = kh * 32 + j * 8;
            const unsigned a0 = __float_as_uint(As[16*m + g    ][kk0 + tig]);
            const unsigned a1 = __float_as_uint(As[16*m + g + 8][kk0 + tig]);
            const unsigned a2 = __float_as_uint(As[16*m + g    ][kk0 + tig + 4]);
            const unsigned a3 = __float_as_uint(As[16*m + g + 8][kk0 + tig + 4]);
            #pragma unroll
            for (int nt = 0; nt < 4; nt++) {
                const int cb = 32*nq + 8*nt + g;
                const unsigned b0 = __float_as_uint(Bs[cb][kk0 + tig]);
                const unsigned b1 = __float_as_uint(Bs[cb][kk0 + tig + 4]);
                asm volatile(
                    "mma.sync.aligned.m16n8k8.row.col.f32.tf32.tf32.f32 "
                    "{%0,%1,%2,%3}, {%4,%5,%6,%7}, {%8,%9}, {%0,%1,%2,%3};"
                    : "+f"(acc[nt][0]), "+f"(acc[nt][1]),
                      "+f"(acc[nt][2]), "+f"(acc[nt][3])
                    : "r"(a0), "r"(a1), "r"(a2), "r"(a3), "r"(b0), "r"(b1));
            }
        }
        __syncthreads();   // compute done before overwriting As/Bs
    }

    // ---- merge kh=1 accumulators into kh=0 warps (scratch aliased on Bs) ----
    if (kh == 1) {
        #pragma unroll
        for (int nt = 0; nt < 4; nt++)
            #pragma unroll
            for (int e = 0; e < 4; e++)
                saccf[(w8 * 32 + lane) * 16 + nt * 4 + e] = acc[nt][e];
    }
    __syncthreads();
    if (kh == 0) {
        #pragma unroll
        for (int nt = 0; nt < 4; nt++)
            #pragma unroll
            for (int e = 0; e < 4; e++)
                acc[nt][e] += saccf[(w8 * 32 + lane) * 16 + nt * 4 + e];
    }

    // ---- Epilogue (R10-validated layout), kh=0 warps only ----
    const int r0 = 16*m + g, r1 = r0 + 8;
    if (kh == 0) {
        float s0 = 0.f, s1 = 0.f;
        #pragma unroll
        for (int nt = 0; nt < 4; nt++) {
            s0 += acc[nt][0] + acc[nt][1];
            s1 += acc[nt][2] + acc[nt][3];
        }
        s0 += __shfl_xor_sync(0xffffffffu, s0, 1);
        s0 += __shfl_xor_sync(0xffffffffu, s0, 2);
        s1 += __shfl_xor_sync(0xffffffffu, s1, 1);
        s1 += __shfl_xor_sync(0xffffffffu, s1, 2);
        if (tig == 0) { Ssm[r0][nq] = s0; Ssm[r1][nq] = s1; }
    }
    __syncthreads();

    if (kh == 0) {
        const float S0 = Ssm[r0][0] + Ssm[r0][1] + Ssm[r0][2] + Ssm[r0][3];
        const float S1 = Ssm[r1][0] + Ssm[r1][1] + Ssm[r1][2] + Ssm[r1][3];
        float pn = 0.f;
        #pragma unroll
        for (int nt = 0; nt < 4; nt++) {
            const int cA = 32*nq + 8*nt + 2*tig;
            const float nA = nsm[cA], nB = nsm[cA + 1];
            pn += nA * __expf(S0 - acc[nt][0]) + nB * __expf(S0 - acc[nt][1]);
            pn += nA * __expf(S1 - acc[nt][2]) + nB * __expf(S1 - acc[nt][3]);
        }
        #pragma unroll
        for (int off = 16; off > 0; off >>= 1)
            pn += __shfl_xor_sync(0xffffffffu, pn, off);

        double warp_sd = 0.0, warp_se = 0.0;
        if (warp == 0) {
            const float dv = g_d[row0 + lane];
            double sd = (double)dv;
            double se = (double)__expf(dv);
            #pragma unroll
            for (int off = 16; off > 0; off >>= 1) {
                sd += __shfl_xor_sync(0xffffffffu, sd, off);
                se += __shfl_xor_sync(0xffffffffu, se, off);
            }
            warp_sd = sd; warp_se = se;
        }
        if (lane == 0) { bred[w8][0] = (double)pn; bred[w8][1] = warp_sd; bred[w8][2] = warp_se; }
    }
    __syncthreads();

    if (tid == 0) {
        double bneg = 0.0;
        #pragma unroll
        for (int w = 0; w < 8; w++) bneg += bred[w][0];
        atomicAdd(&g_neg[p], bneg);
        atomicAdd(&g_sumd[p], bred[0][1]);
        atomicAdd(&g_sumexpd[p], bred[0][2]);
        __threadfence();   // orders scalar adds + buffer-q cleaning stores
        unsigned t = atomicAdd(&g_fin[p], 1u);
        if (t == NBLK - 1) {
            // loss = N*log(neg) + sumexp/neg - sumd (validated across rounds)
            const double neg  = atomicAdd(&g_neg[p], 0.0);
            const double sd   = atomicAdd(&g_sumd[p], 0.0);
            const double sexp = atomicAdd(&g_sumexpd[p], 0.0);
            out[0] = (float)((double)N * log(neg) + sexp / neg - sd);
            __threadfence();
            g_parity = q;
        }
    }
}

// ---------------------------------------------------------------------------
extern "C" void kernel_launch(void* const* d_in, const int* in_sizes, int n_in,
                              void* d_out, int out_size) {
    const float* img    = (const float*)d_in[0];
    const float* txt    = (const float*)d_in[1];
    const int*   labels = (const int*)d_in[2];
    float* out = (float*)d_out;

    rownorm_kernel<<<N, 128>>>(img, txt, labels);
    gemm_neg_kernel<<<NBLK, TPB>>>(txt, out);
}